// round 12
// baseline (speedup 1.0000x reference)
#include <cuda_runtime.h>
#include <cuda_bf16.h>

#define NN 50000
#define NPAD 50048
#define EE 1600000
#define RR 7
#define DD 128
#define GG 64
#define NRSEG (NN * RR)          // 350000
#define CAP 40                   // max edges per (node,rel) segment; P(overflow)~1e-30

// ---------------- static device scratch ------------------------------------
__device__ float g_x[2][(size_t)NPAD * DD];
__device__ __nv_bfloat16 g_xh[(size_t)NPAD * DD];
__device__ __nv_bfloat16 g_xl[(size_t)NPAD * DD];
__device__ __nv_bfloat16 g_uh[(size_t)NPAD * 896];
__device__ __nv_bfloat16 g_ul[(size_t)NPAD * 896];
__device__ __nv_bfloat16 g_Wh[3 * 128 * 1024];   // [L][n][k] transposed, k-contig
__device__ __nv_bfloat16 g_Wl[3 * 128 * 1024];
__device__ float g_bias[3 * 128];
__device__ int   g_counts[NRSEG];
__device__ __align__(16) int2 g_bucket[(size_t)NRSEG * CAP];  // padded edge buckets

// ---------------- helpers ----------------------------------------------------
__device__ __forceinline__ unsigned s2u(const void* p) {
    unsigned a;
    asm("{ .reg .u64 t; cvta.to.shared.u64 t, %1; cvt.u32.u64 %0, t; }" : "=r"(a) : "l"(p));
    return a;
}
__device__ __forceinline__ void cp16(unsigned dst, const void* src) {
    asm volatile("cp.async.cg.shared.global [%0], [%1], 16;" :: "r"(dst), "l"(src) : "memory");
}
__device__ __forceinline__ unsigned long long mk_evict_first() {
    unsigned long long p;
    asm("createpolicy.fractional.L2::evict_first.b64 %0, 1.0;" : "=l"(p));
    return p;
}
__device__ __forceinline__ unsigned long long mk_evict_last() {
    unsigned long long p;
    asm("createpolicy.fractional.L2::evict_last.b64 %0, 1.0;" : "=l"(p));
    return p;
}
__device__ __forceinline__ void cp16_ef(unsigned dst, const void* src,
                                        unsigned long long pol) {
    asm volatile("cp.async.cg.shared.global.L2::cache_hint [%0], [%1], 16, %2;"
                 :: "r"(dst), "l"(src), "l"(pol) : "memory");
}
__device__ __forceinline__ void cp_commit() { asm volatile("cp.async.commit_group;" ::: "memory"); }
__device__ __forceinline__ void cp_wait1()  { asm volatile("cp.async.wait_group 1;" ::: "memory"); }
__device__ __forceinline__ void cp_wait0()  { asm volatile("cp.async.wait_group 0;" ::: "memory"); }
__device__ __forceinline__ void stcs8(void* p, unsigned x, unsigned y) {
    asm volatile("st.global.cs.v2.b32 [%0], {%1, %2};" :: "l"(p), "r"(x), "r"(y) : "memory");
}
__device__ __forceinline__ float4 ldg_el(const float4* p, unsigned long long pol) {
    float4 v;
    asm volatile("ld.global.nc.L2::cache_hint.v4.f32 {%0,%1,%2,%3}, [%4], %5;"
                 : "=f"(v.x), "=f"(v.y), "=f"(v.z), "=f"(v.w) : "l"(p), "l"(pol));
    return v;
}

__device__ __forceinline__ void mma16816(float* c, const unsigned* a, const unsigned* b) {
    asm volatile(
        "mma.sync.aligned.m16n8k16.row.col.f32.bf16.bf16.f32 "
        "{%0,%1,%2,%3}, {%4,%5,%6,%7}, {%8,%9}, {%0,%1,%2,%3};"
        : "+f"(c[0]), "+f"(c[1]), "+f"(c[2]), "+f"(c[3])
        : "r"(a[0]), "r"(a[1]), "r"(a[2]), "r"(a[3]), "r"(b[0]), "r"(b[1]));
}

// ---------------- fused setup (launch 0) ------------------------------------
__global__ void k_setup(const int* __restrict__ unit_type,
                        const float* __restrict__ emb,
                        const float* __restrict__ Wrel,
                        const float* __restrict__ Wloop,
                        const float* __restrict__ brel,
                        const float* __restrict__ bloop,
                        float* __restrict__ out_gf) {
    int i = blockIdx.x * blockDim.x + threadIdx.x;
    if (i < NN * DD) {
        int n = i >> 7, d = i & 127;
        float v = emb[unit_type[n] * DD + d];
        g_x[0][i] = v;
        __nv_bfloat16 h = __float2bfloat16(v);
        g_xh[i] = h;
        g_xl[i] = __float2bfloat16(v - __bfloat162float(h));
    }
    if (i < 3 * 128 * 1024) {
        int L = i >> 17;
        int r = i & 131071;
        int n = r >> 10;
        int k = r & 1023;
        float w = (k < 896) ? Wrel[((size_t)L * 896 + k) * 128 + n]
                            : Wloop[((size_t)L * 128 + (k - 896)) * 128 + n];
        __nv_bfloat16 h = __float2bfloat16(w);
        g_Wh[i] = h;
        g_Wl[i] = __float2bfloat16(w - __bfloat162float(h));
    }
    if (i < NRSEG) g_counts[i] = 0;
    if (i < 3 * 128) g_bias[i] = brel[i] + bloop[i];
    if (i < GG * DD) out_gf[i] = 0.0f;
}

// ---------------- bucket build (launch 1): no hist, no scan ------------------
__global__ void k_fill(const int* __restrict__ node_in,
                       const int* __restrict__ node_out,
                       const int* __restrict__ rel,
                       const float* __restrict__ ew) {
    int i = blockIdx.x * blockDim.x + threadIdx.x;
    if (i >= EE) return;
    int seg = node_out[i] * RR + rel[i];
    int p = atomicAdd(&g_counts[seg], 1);
    if (p < CAP)
        g_bucket[(size_t)seg * CAP + p] = make_int2(node_in[i], __float_as_int(ew[i]));
}

// ---------------- per-layer edge scatter -> bf16 hi/lo -----------------------
// One warp per segment; 4-wide edge unroll with int4 broadcast meta loads;
// x gathers evict_last (keep resident); upd writes st.cs (don't pollute L2).
__global__ void k_scatter(int layer) {
    int gw   = (blockIdx.x * blockDim.x + threadIdx.x) >> 5;
    int lane = threadIdx.x & 31;
    if (gw >= NRSEG) return;
    const float4* __restrict__ xv = (const float4*)g_x[layer & 1];
    unsigned long long pol = mk_evict_last();
    int cnt = min(g_counts[gw], CAP);
    const int2* __restrict__ bkt = g_bucket + (size_t)gw * CAP;

    float4 a0 = make_float4(0.f, 0.f, 0.f, 0.f);
    float4 a1 = a0, a2 = a0, a3 = a0;
    int e = 0;
    for (; e + 4 <= cnt; e += 4) {
        int4 m01 = *(const int4*)(bkt + e);       // edges e, e+1 (broadcast)
        int4 m23 = *(const int4*)(bkt + e + 2);   // edges e+2, e+3
        float4 v0 = ldg_el(xv + (size_t)m01.x * 32 + lane, pol);
        float4 v1 = ldg_el(xv + (size_t)m01.z * 32 + lane, pol);
        float4 v2 = ldg_el(xv + (size_t)m23.x * 32 + lane, pol);
        float4 v3 = ldg_el(xv + (size_t)m23.z * 32 + lane, pol);
        float w0 = __int_as_float(m01.y), w1 = __int_as_float(m01.w);
        float w2 = __int_as_float(m23.y), w3 = __int_as_float(m23.w);
        a0.x += v0.x * w0; a0.y += v0.y * w0; a0.z += v0.z * w0; a0.w += v0.w * w0;
        a1.x += v1.x * w1; a1.y += v1.y * w1; a1.z += v1.z * w1; a1.w += v1.w * w1;
        a2.x += v2.x * w2; a2.y += v2.y * w2; a2.z += v2.z * w2; a2.w += v2.w * w2;
        a3.x += v3.x * w3; a3.y += v3.y * w3; a3.z += v3.z * w3; a3.w += v3.w * w3;
    }
    for (; e < cnt; ++e) {
        int2 m = bkt[e];
        float4 v = ldg_el(xv + (size_t)m.x * 32 + lane, pol);
        float w = __int_as_float(m.y);
        a0.x += v.x * w; a0.y += v.y * w; a0.z += v.z * w; a0.w += v.w * w;
    }
    float4 acc = make_float4(a0.x + a1.x + a2.x + a3.x,
                             a0.y + a1.y + a2.y + a3.y,
                             a0.z + a1.z + a2.z + a3.z,
                             a0.w + a1.w + a2.w + a3.w);

    size_t o = (size_t)gw * 128 + lane * 4;
    __nv_bfloat16 h0 = __float2bfloat16(acc.x);
    __nv_bfloat16 h1 = __float2bfloat16(acc.y);
    __nv_bfloat16 h2 = __float2bfloat16(acc.z);
    __nv_bfloat16 h3 = __float2bfloat16(acc.w);
    __nv_bfloat162 a, b; a.x = h0; a.y = h1; b.x = h2; b.y = h3;
    __nv_bfloat162 c, d;
    c.x = __float2bfloat16(acc.x - __bfloat162float(h0));
    c.y = __float2bfloat16(acc.y - __bfloat162float(h1));
    d.x = __float2bfloat16(acc.z - __bfloat162float(h2));
    d.y = __float2bfloat16(acc.w - __bfloat162float(h3));
    stcs8(g_uh + o, *(unsigned*)&a, *(unsigned*)&b);
    stcs8(g_ul + o, *(unsigned*)&c, *(unsigned*)&d);
}

// ---------------- mma.sync GEMM: h = [upd|x] @ W + b, relu -------------------
// CTA: 128 rows x 128 cols, K=1024 (896 upd + 128 x), BK=64, double-buffered
// cp.async. 3-term bf16 split into fp32 accum: Ah*Bh + Ah*Bl + Al*Bh.
// A tiles (read-once) use L2::evict_first to protect x/edges residency.
#define TSTRIDE 72
#define TBYTES  (128 * TSTRIDE * 2)          // 18432 per tile
#define STAGEB  (4 * TBYTES)                 // Ah,Al,Bh,Bl = 73728
#define SMTOT   (2 * STAGEB)                 // 147456

__device__ __forceinline__ void load_chunk(char* sm, int stage, int c,
                                           int row0, int layer, int tid,
                                           unsigned long long pol) {
    unsigned base = s2u(sm) + (unsigned)stage * STAGEB;
    const __nv_bfloat16* wh = g_Wh + (size_t)layer * 131072;
    const __nv_bfloat16* wl = g_Wl + (size_t)layer * 131072;
    #pragma unroll
    for (int i = 0; i < 16; i++) {
        int idx = tid + 256 * i;             // 4096 x 16B units
        int arr = idx >> 10;
        int rem = idx & 1023;
        int row = rem >> 3;
        int seg = rem & 7;
        unsigned dst = base + (unsigned)arr * TBYTES + row * 144u + seg * 16u;
        if (arr < 2) {                        // A (hi / lo): evict-first stream
            const __nv_bfloat16* src;
            if (c < 14) {
                size_t o = (size_t)(row0 + row) * 896 + c * 64 + seg * 8;
                src = (arr == 0 ? g_uh : g_ul) + o;
            } else {
                size_t o = (size_t)(row0 + row) * 128 + (c - 14) * 64 + seg * 8;
                src = (arr == 0 ? g_xh : g_xl) + o;
            }
            cp16_ef(dst, src, pol);
        } else {                              // B (hi / lo): small, keep cached
            size_t o = (size_t)row * 1024 + c * 64 + seg * 8;
            cp16(dst, (arr == 2 ? wh : wl) + o);
        }
    }
}

__global__ void __launch_bounds__(256, 1)
k_gemm(int layer, float* __restrict__ xout_ext, int dosplit) {
    extern __shared__ char sm[];
    __shared__ float s_bias[128];

    int tid  = threadIdx.x;
    int wid  = tid >> 5, lane = tid & 31;
    int wm   = wid & 1;                      // 2 warps in m
    int wn   = wid >> 1;                     // 4 warps in n
    int row0 = blockIdx.x * 128;
    float* __restrict__ xout = xout_ext ? xout_ext : g_x[(layer + 1) & 1];
    unsigned long long pol = mk_evict_first();

    if (tid < 128) s_bias[tid] = g_bias[layer * 128 + tid];

    float acc[4][4][4];
    #pragma unroll
    for (int a = 0; a < 4; a++)
        #pragma unroll
        for (int b = 0; b < 4; b++)
            #pragma unroll
            for (int e = 0; e < 4; e++) acc[a][b][e] = 0.f;

    load_chunk(sm, 0, 0, row0, layer, tid, pol);
    cp_commit();

    const int g = lane >> 2, q = lane & 3;
    for (int c = 0; c < 16; ++c) {
        if (c < 15) {
            load_chunk(sm, (c + 1) & 1, c + 1, row0, layer, tid, pol);
            cp_commit();
            cp_wait1();
        } else {
            cp_wait0();
        }
        __syncthreads();

        const char* st = sm + (c & 1) * STAGEB;
        const char* Ah = st;
        const char* Al = st + TBYTES;
        const char* Bh = st + 2 * TBYTES;
        const char* Bl = st + 3 * TBYTES;

        #pragma unroll
        for (int ks = 0; ks < 4; ++ks) {
            int k0 = ks * 16 + 2 * q;        // bf16 element index in row
            unsigned ah[4][4], al_[4][4], bh[4][2], bl[4][2];
            #pragma unroll
            for (int mt = 0; mt < 4; ++mt) {
                int r = wm * 64 + mt * 16 + g;
                ah[mt][0] = *(const unsigned*)(Ah + r * 144 + k0 * 2);
                ah[mt][1] = *(const unsigned*)(Ah + (r + 8) * 144 + k0 * 2);
                ah[mt][2] = *(const unsigned*)(Ah + r * 144 + (k0 + 8) * 2);
                ah[mt][3] = *(const unsigned*)(Ah + (r + 8) * 144 + (k0 + 8) * 2);
                al_[mt][0] = *(const unsigned*)(Al + r * 144 + k0 * 2);
                al_[mt][1] = *(const unsigned*)(Al + (r + 8) * 144 + k0 * 2);
                al_[mt][2] = *(const unsigned*)(Al + r * 144 + (k0 + 8) * 2);
                al_[mt][3] = *(const unsigned*)(Al + (r + 8) * 144 + (k0 + 8) * 2);
            }
            #pragma unroll
            for (int nt = 0; nt < 4; ++nt) {
                int n = wn * 32 + nt * 8 + g;
                bh[nt][0] = *(const unsigned*)(Bh + n * 144 + k0 * 2);
                bh[nt][1] = *(const unsigned*)(Bh + n * 144 + (k0 + 8) * 2);
                bl[nt][0] = *(const unsigned*)(Bl + n * 144 + k0 * 2);
                bl[nt][1] = *(const unsigned*)(Bl + n * 144 + (k0 + 8) * 2);
            }
            #pragma unroll
            for (int mt = 0; mt < 4; ++mt)
                #pragma unroll
                for (int nt = 0; nt < 4; ++nt) {
                    mma16816(acc[mt][nt], ah[mt],  bh[nt]);
                    mma16816(acc[mt][nt], ah[mt],  bl[nt]);
                    mma16816(acc[mt][nt], al_[mt], bh[nt]);
                }
        }
        __syncthreads();
    }

    // epilogue: bias + relu, fp32 store (+ bf16 split for next layer)
    #pragma unroll
    for (int mt = 0; mt < 4; ++mt) {
        int m0 = row0 + wm * 64 + mt * 16 + g;
        #pragma unroll
        for (int nt = 0; nt < 4; ++nt) {
            int col = wn * 32 + nt * 8 + 2 * q;
            float b0 = s_bias[col], b1 = s_bias[col + 1];
            #pragma unroll
            for (int half = 0; half < 2; ++half) {
                int m = m0 + half * 8;
                if (m >= NN) continue;
                float v0 = fmaxf(acc[mt][nt][2 * half]     + b0, 0.f);
                float v1 = fmaxf(acc[mt][nt][2 * half + 1] + b1, 0.f);
                float2* dst = (float2*)(xout + (size_t)m * 128 + col);
                *dst = make_float2(v0, v1);
                if (dosplit) {
                    __nv_bfloat16 h0 = __float2bfloat16(v0);
                    __nv_bfloat16 h1 = __float2bfloat16(v1);
                    __nv_bfloat162 hh; hh.x = h0; hh.y = h1;
                    *(unsigned*)(g_xh + (size_t)m * 128 + col) = *(unsigned*)&hh;
                    __nv_bfloat162 ll;
                    ll.x = __float2bfloat16(v0 - __bfloat162float(h0));
                    ll.y = __float2bfloat16(v1 - __bfloat162float(h1));
                    *(unsigned*)(g_xl + (size_t)m * 128 + col) = *(unsigned*)&ll;
                }
            }
        }
    }
}

// ---------------- graph pooling (node2graph sorted) --------------------------
__global__ void k_segsum(const float* __restrict__ x,
                         const int* __restrict__ n2g,
                         float* __restrict__ out) {
    int d  = threadIdx.x;
    int r0 = blockIdx.x * 512;
    if (r0 >= NN) return;
    int r1 = min(r0 + 512, NN);
    float acc = 0.f;
    int gcur = n2g[r0];
    for (int r = r0; r < r1; ++r) {
        int g = n2g[r];
        if (g != gcur) {
            atomicAdd(&out[gcur * DD + d], acc);
            acc = 0.f; gcur = g;
        }
        acc += x[(size_t)r * DD + d];
    }
    atomicAdd(&out[gcur * DD + d], acc);
}

// ---------------- launch -----------------------------------------------------
// Launch order is load-bearing for profiling: ncu empirically captures launch
// index 3 — which is now k_gemm(layer 0).
extern "C" void kernel_launch(void* const* d_in, const int* in_sizes, int n_in,
                              void* d_out, int out_size) {
    const int*   unit_type   = (const int*)  d_in[0];
    const int*   node_in     = (const int*)  d_in[1];
    const int*   node_out    = (const int*)  d_in[2];
    const int*   relation    = (const int*)  d_in[3];
    const float* edge_weight = (const float*)d_in[4];
    const int*   node2graph  = (const int*)  d_in[5];
    const float* emb         = (const float*)d_in[6];
    const float* W_rel       = (const float*)d_in[7];
    const float* b_rel       = (const float*)d_in[8];
    const float* W_loop      = (const float*)d_in[9];
    const float* b_loop      = (const float*)d_in[10];

    float* out    = (float*)d_out;
    float* out_gf = out;
    float* out_x  = out + GG * DD;

    cudaFuncSetAttribute(k_gemm, cudaFuncAttributeMaxDynamicSharedMemorySize, SMTOT);

    k_setup<<<(NN * DD + 255) / 256, 256>>>(unit_type, emb, W_rel, W_loop,
                                            b_rel, b_loop, out_gf);          // 0
    k_fill<<<(EE + 255) / 256, 256>>>(node_in, node_out, relation,
                                      edge_weight);                          // 1

    for (int L = 0; L < 3; ++L) {
        k_scatter<<<(NRSEG * 32 + 255) / 256, 256>>>(L);                     // 2,4,6
        float* oext = (L == 2) ? out_x : nullptr;
        k_gemm<<<(NN + 127) / 128, 256, SMTOT>>>(L, oext, (L < 2) ? 1 : 0);  // 3 <- ncu
    }

    k_segsum<<<(NN + 511) / 512, 128>>>(out_x, node2graph, out_gf);
}

// round 15
// speedup vs baseline: 1.0171x; 1.0171x over previous
#include <cuda_runtime.h>
#include <cuda_bf16.h>

#define NN 50000
#define NPAD 50048
#define EE 1600000
#define RR 7
#define DD 128
#define GG 64
#define NRSEG (NN * RR)          // 350000
#define SCAN_B 1024
#define NB1 ((NRSEG + SCAN_B - 1) / SCAN_B)   // 342

// ---------------- static device scratch ------------------------------------
__device__ float g_x[2][(size_t)NPAD * DD];
__device__ __nv_bfloat16 g_xh[(size_t)NPAD * DD];
__device__ __nv_bfloat16 g_xl[(size_t)NPAD * DD];
__device__ __nv_bfloat16 g_uh[(size_t)NPAD * 896];
__device__ __nv_bfloat16 g_ul[(size_t)NPAD * 896];
__device__ __nv_bfloat16 g_Wh[3 * 128 * 1024];   // [L][n][k] transposed, k-contig
__device__ __nv_bfloat16 g_Wl[3 * 128 * 1024];
__device__ float g_bias[3 * 128];
__device__ int   g_counts[NRSEG];                // zero at load; re-zeroed by k_scan
__device__ int   g_offs[NRSEG + 1];
__device__ int   g_cursor[NRSEG];
__device__ unsigned long long g_scanstate[NB1];  // zero at load; re-zeroed by k_fill
__device__ int2  g_edge[EE];                     // (src, w-bits), segment-sorted

// ---------------- helpers ----------------------------------------------------
__device__ __forceinline__ unsigned s2u(const void* p) {
    unsigned a;
    asm("{ .reg .u64 t; cvta.to.shared.u64 t, %1; cvt.u32.u64 %0, t; }" : "=r"(a) : "l"(p));
    return a;
}
__device__ __forceinline__ void cp16(unsigned dst, const void* src) {
    asm volatile("cp.async.cg.shared.global [%0], [%1], 16;" :: "r"(dst), "l"(src) : "memory");
}
__device__ __forceinline__ unsigned long long mk_evict_first() {
    unsigned long long p;
    asm("createpolicy.fractional.L2::evict_first.b64 %0, 1.0;" : "=l"(p));
    return p;
}
__device__ __forceinline__ unsigned long long mk_evict_last() {
    unsigned long long p;
    asm("createpolicy.fractional.L2::evict_last.b64 %0, 1.0;" : "=l"(p));
    return p;
}
__device__ __forceinline__ void cp16_ef(unsigned dst, const void* src,
                                        unsigned long long pol) {
    asm volatile("cp.async.cg.shared.global.L2::cache_hint [%0], [%1], 16, %2;"
                 :: "r"(dst), "l"(src), "l"(pol) : "memory");
}
__device__ __forceinline__ void cp_commit() { asm volatile("cp.async.commit_group;" ::: "memory"); }
__device__ __forceinline__ void cp_wait1()  { asm volatile("cp.async.wait_group 1;" ::: "memory"); }
__device__ __forceinline__ void cp_wait0()  { asm volatile("cp.async.wait_group 0;" ::: "memory"); }
__device__ __forceinline__ void stcs8(void* p, unsigned x, unsigned y) {
    asm volatile("st.global.cs.v2.b32 [%0], {%1, %2};" :: "l"(p), "r"(x), "r"(y) : "memory");
}
__device__ __forceinline__ float4 ldg_el(const float4* p, unsigned long long pol) {
    float4 v;
    asm volatile("ld.global.nc.L2::cache_hint.v4.f32 {%0,%1,%2,%3}, [%4], %5;"
                 : "=f"(v.x), "=f"(v.y), "=f"(v.z), "=f"(v.w) : "l"(p), "l"(pol));
    return v;
}
__device__ __forceinline__ void st_rel(unsigned long long* p, unsigned long long v) {
    asm volatile("st.release.gpu.u64 [%0], %1;" :: "l"(p), "l"(v) : "memory");
}
__device__ __forceinline__ unsigned long long ld_acq(unsigned long long* p) {
    unsigned long long v;
    asm volatile("ld.acquire.gpu.u64 %0, [%1];" : "=l"(v) : "l"(p) : "memory");
    return v;
}
__device__ __forceinline__ void ldsm4(unsigned* r, unsigned addr) {
    asm volatile("ldmatrix.sync.aligned.m8n8.x4.shared.b16 {%0,%1,%2,%3}, [%4];"
                 : "=r"(r[0]), "=r"(r[1]), "=r"(r[2]), "=r"(r[3]) : "r"(addr));
}
__device__ __forceinline__ void mma16816(float* c, const unsigned* a, const unsigned* b) {
    asm volatile(
        "mma.sync.aligned.m16n8k16.row.col.f32.bf16.bf16.f32 "
        "{%0,%1,%2,%3}, {%4,%5,%6,%7}, {%8,%9}, {%0,%1,%2,%3};"
        : "+f"(c[0]), "+f"(c[1]), "+f"(c[2]), "+f"(c[3])
        : "r"(a[0]), "r"(a[1]), "r"(a[2]), "r"(a[3]), "r"(b[0]), "r"(b[1]));
}

// ---------------- fused setup + hist (launch 0) ------------------------------
// g_counts is zero on entry (module init on run 1; k_scan re-zeroes each run).
__global__ void k_setup(const int* __restrict__ unit_type,
                        const float* __restrict__ emb,
                        const float* __restrict__ Wrel,
                        const float* __restrict__ Wloop,
                        const float* __restrict__ brel,
                        const float* __restrict__ bloop,
                        const int* __restrict__ node_out,
                        const int* __restrict__ rel,
                        float* __restrict__ out_gf) {
    int i = blockIdx.x * blockDim.x + threadIdx.x;
    if (i < NN * DD) {
        int n = i >> 7, d = i & 127;
        float v = emb[unit_type[n] * DD + d];
        g_x[0][i] = v;
        __nv_bfloat16 h = __float2bfloat16(v);
        g_xh[i] = h;
        g_xl[i] = __float2bfloat16(v - __bfloat162float(h));
    }
    if (i < 3 * 128 * 1024) {
        int L = i >> 17;
        int r = i & 131071;
        int n = r >> 10;
        int k = r & 1023;
        float w = (k < 896) ? Wrel[((size_t)L * 896 + k) * 128 + n]
                            : Wloop[((size_t)L * 128 + (k - 896)) * 128 + n];
        __nv_bfloat16 h = __float2bfloat16(w);
        g_Wh[i] = h;
        g_Wl[i] = __float2bfloat16(w - __bfloat162float(h));
    }
    if (i < EE) atomicAdd(&g_counts[node_out[i] * RR + rel[i]], 1);
    if (i < 3 * 128) g_bias[i] = brel[i] + bloop[i];
    if (i < GG * DD) out_gf[i] = 0.0f;
}

// ---------------- scan (launch 1): decoupled lookback; re-zeroes counts ------
__global__ void k_scan() {
    __shared__ int s[SCAN_B];
    __shared__ int s_prefix;
    int bid = blockIdx.x, tid = threadIdx.x;
    int i = bid * SCAN_B + tid;
    int v = (i < NRSEG) ? g_counts[i] : 0;
    if (i < NRSEG) g_counts[i] = 0;           // replay-safety for next run's hist
    s[tid] = v;
    __syncthreads();
    #pragma unroll
    for (int off = 1; off < SCAN_B; off <<= 1) {
        int t = (tid >= off) ? s[tid - off] : 0;
        __syncthreads();
        s[tid] += t;
        __syncthreads();
    }
    int incl  = s[tid];
    int total = s[SCAN_B - 1];

    if (tid == 0) {
        if (bid == 0) {
            st_rel(&g_scanstate[0], ((unsigned long long)total << 2) | 2ull);
            s_prefix = 0;
        } else {
            st_rel(&g_scanstate[bid], ((unsigned long long)total << 2) | 1ull);
            int prefix = 0, j = bid - 1;
            while (true) {
                unsigned long long st = ld_acq(&g_scanstate[j]);
                unsigned f = (unsigned)(st & 3ull);
                if (f == 2u) { prefix += (int)(st >> 2); break; }
                if (f == 1u) { prefix += (int)(st >> 2); --j; }
            }
            st_rel(&g_scanstate[bid],
                   ((unsigned long long)(prefix + total) << 2) | 2ull);
            s_prefix = prefix;
        }
    }
    __syncthreads();
    if (i < NRSEG) {
        int excl = s_prefix + incl - v;
        g_offs[i]   = excl;
        g_cursor[i] = excl;
    }
    if (i == 0) g_offs[NRSEG] = EE;
}

// ---------------- fill (launch 2): CSR edges; re-zeroes scanstate ------------
__global__ void k_fill(const int* __restrict__ node_in,
                       const int* __restrict__ node_out,
                       const int* __restrict__ rel,
                       const float* __restrict__ ew) {
    int i = blockIdx.x * blockDim.x + threadIdx.x;
    if (i < NB1) g_scanstate[i] = 0ull;       // replay-safety for next run's scan
    if (i >= EE) return;
    int seg = node_out[i] * RR + rel[i];
    int p = atomicAdd(&g_cursor[seg], 1);
    g_edge[p] = make_int2(node_in[i], __float_as_int(ew[i]));
}

// ---------------- per-layer edge scatter -> bf16 hi/lo -----------------------
// One warp per segment; 4-wide edge unroll (4 independent gather chains);
// x gathers evict_last; upd writes st.cs (don't pollute L2).
__global__ void k_scatter(int layer) {
    int gw   = (blockIdx.x * blockDim.x + threadIdx.x) >> 5;
    int lane = threadIdx.x & 31;
    if (gw >= NRSEG) return;
    const float4* __restrict__ xv = (const float4*)g_x[layer & 1];
    unsigned long long pol = mk_evict_last();
    int beg = g_offs[gw], end = g_offs[gw + 1];

    float4 a0 = make_float4(0.f, 0.f, 0.f, 0.f);
    float4 a1 = a0, a2 = a0, a3 = a0;
    int e = beg;
    for (; e + 4 <= end; e += 4) {
        int2 m0 = g_edge[e],     m1 = g_edge[e + 1];
        int2 m2 = g_edge[e + 2], m3 = g_edge[e + 3];
        float4 v0 = ldg_el(xv + (size_t)m0.x * 32 + lane, pol);
        float4 v1 = ldg_el(xv + (size_t)m1.x * 32 + lane, pol);
        float4 v2 = ldg_el(xv + (size_t)m2.x * 32 + lane, pol);
        float4 v3 = ldg_el(xv + (size_t)m3.x * 32 + lane, pol);
        float w0 = __int_as_float(m0.y), w1 = __int_as_float(m1.y);
        float w2 = __int_as_float(m2.y), w3 = __int_as_float(m3.y);
        a0.x += v0.x * w0; a0.y += v0.y * w0; a0.z += v0.z * w0; a0.w += v0.w * w0;
        a1.x += v1.x * w1; a1.y += v1.y * w1; a1.z += v1.z * w1; a1.w += v1.w * w1;
        a2.x += v2.x * w2; a2.y += v2.y * w2; a2.z += v2.z * w2; a2.w += v2.w * w2;
        a3.x += v3.x * w3; a3.y += v3.y * w3; a3.z += v3.z * w3; a3.w += v3.w * w3;
    }
    for (; e < end; ++e) {
        int2 m = g_edge[e];
        float4 v = ldg_el(xv + (size_t)m.x * 32 + lane, pol);
        float w = __int_as_float(m.y);
        a0.x += v.x * w; a0.y += v.y * w; a0.z += v.z * w; a0.w += v.w * w;
    }
    float4 acc = make_float4(a0.x + a1.x + a2.x + a3.x,
                             a0.y + a1.y + a2.y + a3.y,
                             a0.z + a1.z + a2.z + a3.z,
                             a0.w + a1.w + a2.w + a3.w);

    size_t o = (size_t)gw * 128 + lane * 4;
    __nv_bfloat16 h0 = __float2bfloat16(acc.x);
    __nv_bfloat16 h1 = __float2bfloat16(acc.y);
    __nv_bfloat16 h2 = __float2bfloat16(acc.z);
    __nv_bfloat16 h3 = __float2bfloat16(acc.w);
    __nv_bfloat162 a, b; a.x = h0; a.y = h1; b.x = h2; b.y = h3;
    __nv_bfloat162 c, d;
    c.x = __float2bfloat16(acc.x - __bfloat162float(h0));
    c.y = __float2bfloat16(acc.y - __bfloat162float(h1));
    d.x = __float2bfloat16(acc.z - __bfloat162float(h2));
    d.y = __float2bfloat16(acc.w - __bfloat162float(h3));
    stcs8(g_uh + o, *(unsigned*)&a, *(unsigned*)&b);
    stcs8(g_ul + o, *(unsigned*)&c, *(unsigned*)&d);
}

// ---------------- mma.sync GEMM (512 threads, ldmatrix fragments) ------------
// CTA 128x128, K=1024 virtual (896 upd + 128 x), BK=64, double-buffered
// cp.async. 16 warps as 4(m)x4(n), warp tile 32x32. 3-term bf16 split:
// Ah*Bh + Ah*Bl + Al*Bh into fp32 accum. Fragments via ldmatrix.x4 (144B row
// stride -> 8 rows hit 8 distinct 16B banks: conflict-free).
#define TSTRIDE 72
#define TBYTES  (128 * TSTRIDE * 2)          // 18432 per tile
#define STAGEB  (4 * TBYTES)                 // Ah,Al,Bh,Bl = 73728
#define SMTOT   (2 * STAGEB)                 // 147456

__device__ __forceinline__ void load_chunk(char* sm, int stage, int c,
                                           int row0, int layer, int tid,
                                           unsigned long long pol) {
    unsigned base = s2u(sm) + (unsigned)stage * STAGEB;
    const __nv_bfloat16* wh = g_Wh + (size_t)layer * 131072;
    const __nv_bfloat16* wl = g_Wl + (size_t)layer * 131072;
    #pragma unroll
    for (int i = 0; i < 8; i++) {
        int idx = tid + 512 * i;             // 4096 x 16B units
        int arr = idx >> 10;
        int rem = idx & 1023;
        int row = rem >> 3;
        int seg = rem & 7;
        unsigned dst = base + (unsigned)arr * TBYTES + row * 144u + seg * 16u;
        if (arr < 2) {                        // A (hi / lo): evict-first stream
            const __nv_bfloat16* src;
            if (c < 14) {
                size_t o = (size_t)(row0 + row) * 896 + c * 64 + seg * 8;
                src = (arr == 0 ? g_uh : g_ul) + o;
            } else {
                size_t o = (size_t)(row0 + row) * 128 + (c - 14) * 64 + seg * 8;
                src = (arr == 0 ? g_xh : g_xl) + o;
            }
            cp16_ef(dst, src, pol);
        } else {                              // B (hi / lo): small, keep cached
            size_t o = (size_t)row * 1024 + c * 64 + seg * 8;
            cp16(dst, (arr == 2 ? wh : wl) + o);
        }
    }
}

__global__ void __launch_bounds__(512, 1)
k_gemm(int layer, float* __restrict__ xout_ext, int dosplit) {
    extern __shared__ char sm[];
    __shared__ float s_bias[128];

    int tid  = threadIdx.x;
    int wid  = tid >> 5, lane = tid & 31;
    int wm   = wid >> 2;                     // 4 warps in m (32 rows each)
    int wn   = wid & 3;                      // 4 warps in n (32 cols each)
    int row0 = blockIdx.x * 128;
    float* __restrict__ xout = xout_ext ? xout_ext : g_x[(layer + 1) & 1];
    unsigned long long pol = mk_evict_first();

    if (tid < 128) s_bias[tid] = g_bias[layer * 128 + tid];

    float acc[2][4][4];
    #pragma unroll
    for (int a = 0; a < 2; a++)
        #pragma unroll
        for (int b = 0; b < 4; b++)
            #pragma unroll
            for (int e = 0; e < 4; e++) acc[a][b][e] = 0.f;

    // per-thread ldmatrix row addresses (byte offsets within a tile)
    int quad = lane >> 3, tr = lane & 7;
    unsigned aOff[2], bOff[2];
    #pragma unroll
    for (int mt = 0; mt < 2; mt++)           // A x4: q0=(r,k0) q1=(r+8,k0) q2=(r,k8) q3=(r+8,k8)
        aOff[mt] = (unsigned)((wm * 32 + mt * 16 + (quad & 1) * 8 + tr) * 144
                              + ((quad >> 1) * 8) * 2);
    #pragma unroll
    for (int p = 0; p < 2; p++)              // B x4: q0=(n,k0) q1=(n,k8) q2=(n+8,k0) q3=(n+8,k8)
        bOff[p] = (unsigned)((wn * 32 + p * 16 + (quad >> 1) * 8 + tr) * 144
                             + ((quad & 1) * 8) * 2);

    load_chunk(sm, 0, 0, row0, layer, tid, pol);
    cp_commit();

    const int g = lane >> 2, q = lane & 3;
    for (int c = 0; c < 16; ++c) {
        if (c < 15) {
            load_chunk(sm, (c + 1) & 1, c + 1, row0, layer, tid, pol);
            cp_commit();
            cp_wait1();
        } else {
            cp_wait0();
        }
        __syncthreads();

        unsigned stU = s2u(sm) + (unsigned)(c & 1) * STAGEB;
        unsigned AhU = stU, AlU = stU + TBYTES;
        unsigned BhU = stU + 2 * TBYTES, BlU = stU + 3 * TBYTES;

        #pragma unroll
        for (int ks = 0; ks < 4; ++ks) {
            unsigned ko = (unsigned)ks * 32;     // 16 bf16 = 32 bytes per k-step
            unsigned ah[2][4], al_[2][4], bh[2][4], bl[2][4];
            #pragma unroll
            for (int mt = 0; mt < 2; ++mt) {
                ldsm4(ah[mt],  AhU + aOff[mt] + ko);
                ldsm4(al_[mt], AlU + aOff[mt] + ko);
            }
            #pragma unroll
            for (int p = 0; p < 2; ++p) {
                ldsm4(bh[p], BhU + bOff[p] + ko);
                ldsm4(bl[p], BlU + bOff[p] + ko);
            }
            #pragma unroll
            for (int mt = 0; mt < 2; ++mt)
                #pragma unroll
                for (int nt = 0; nt < 4; ++nt) {
                    int p = nt >> 1, i0 = (nt & 1) * 2;
                    mma16816(acc[mt][nt], ah[mt],  &bh[p][i0]);
                    mma16816(acc[mt][nt], ah[mt],  &bl[p][i0]);
                    mma16816(acc[mt][nt], al_[mt], &bh[p][i0]);
                }
        }
        __syncthreads();
    }

    // epilogue: bias + relu, fp32 store (+ bf16 split for next layer)
    #pragma unroll
    for (int mt = 0; mt < 2; ++mt) {
        int m0 = row0 + wm * 32 + mt * 16 + g;
        #pragma unroll
        for (int nt = 0; nt < 4; ++nt) {
            int col = wn * 32 + nt * 8 + 2 * q;
            float b0 = s_bias[col], b1 = s_bias[col + 1];
            #pragma unroll
            for (int half = 0; half < 2; ++half) {
                int m = m0 + half * 8;
                if (m >= NN) continue;
                float v0 = fmaxf(acc[mt][nt][2 * half]     + b0, 0.f);
                float v1 = fmaxf(acc[mt][nt][2 * half + 1] + b1, 0.f);
                *(float2*)(xout + (size_t)m * 128 + col) = make_float2(v0, v1);
                if (dosplit) {
                    __nv_bfloat16 h0 = __float2bfloat16(v0);
                    __nv_bfloat16 h1 = __float2bfloat16(v1);
                    __nv_bfloat162 hh; hh.x = h0; hh.y = h1;
                    *(unsigned*)(g_xh + (size_t)m * 128 + col) = *(unsigned*)&hh;
                    __nv_bfloat162 ll;
                    ll.x = __float2bfloat16(v0 - __bfloat162float(h0));
                    ll.y = __float2bfloat16(v1 - __bfloat162float(h1));
                    *(unsigned*)(g_xl + (size_t)m * 128 + col) = *(unsigned*)&ll;
                }
            }
        }
    }
}

// ---------------- graph pooling (node2graph sorted) --------------------------
__global__ void k_segsum(const float* __restrict__ x,
                         const int* __restrict__ n2g,
                         float* __restrict__ out) {
    int d  = threadIdx.x;
    int r0 = blockIdx.x * 512;
    if (r0 >= NN) return;
    int r1 = min(r0 + 512, NN);
    float acc = 0.f;
    int gcur = n2g[r0];
    for (int r = r0; r < r1; ++r) {
        int g = n2g[r];
        if (g != gcur) {
            atomicAdd(&out[gcur * DD + d], acc);
            acc = 0.f; gcur = g;
        }
        acc += x[(size_t)r * DD + d];
    }
    atomicAdd(&out[gcur * DD + d], acc);
}

// ---------------- launch -----------------------------------------------------
// Launch order is load-bearing for profiling: ncu empirically captures launch
// index 3 — which is now k_scatter(layer 0).
extern "C" void kernel_launch(void* const* d_in, const int* in_sizes, int n_in,
                              void* d_out, int out_size) {
    const int*   unit_type   = (const int*)  d_in[0];
    const int*   node_in     = (const int*)  d_in[1];
    const int*   node_out    = (const int*)  d_in[2];
    const int*   relation    = (const int*)  d_in[3];
    const float* edge_weight = (const float*)d_in[4];
    const int*   node2graph  = (const int*)  d_in[5];
    const float* emb         = (const float*)d_in[6];
    const float* W_rel       = (const float*)d_in[7];
    const float* b_rel       = (const float*)d_in[8];
    const float* W_loop      = (const float*)d_in[9];
    const float* b_loop      = (const float*)d_in[10];

    float* out    = (float*)d_out;
    float* out_gf = out;
    float* out_x  = out + GG * DD;

    cudaFuncSetAttribute(k_gemm, cudaFuncAttributeMaxDynamicSharedMemorySize, SMTOT);

    k_setup<<<(NN * DD + 255) / 256, 256>>>(unit_type, emb, W_rel, W_loop,
                                            b_rel, b_loop, node_out, relation,
                                            out_gf);                         // 0
    k_scan<<<NB1, SCAN_B>>>();                                               // 1
    k_fill<<<(EE + 255) / 256, 256>>>(node_in, node_out, relation,
                                      edge_weight);                          // 2

    for (int L = 0; L < 3; ++L) {
        k_scatter<<<(NRSEG * 32 + 255) / 256, 256>>>(L);                     // 3 <- ncu
        float* oext = (L == 2) ? out_x : nullptr;
        k_gemm<<<(NN + 127) / 128, 512, SMTOT>>>(L, oext, (L < 2) ? 1 : 0);
    }

    k_segsum<<<(NN + 511) / 512, 128>>>(out_x, node2graph, out_gf);
}

// round 16
// speedup vs baseline: 1.0218x; 1.0046x over previous
#include <cuda_runtime.h>
#include <cuda_bf16.h>

#define NN 50000
#define NPAD 50048
#define EE 1600000
#define RR 7
#define DD 128
#define GG 64
#define NRSEG (NN * RR)          // 350000
#define SCAN_B 1024
#define NB1 ((NRSEG + SCAN_B - 1) / SCAN_B)   // 342

// ---------------- static device scratch ------------------------------------
__device__ float g_x[2][(size_t)NPAD * DD];
__device__ __nv_bfloat16 g_xh[(size_t)NPAD * DD];
__device__ __nv_bfloat16 g_xl[(size_t)NPAD * DD];
__device__ __nv_bfloat16 g_uh[(size_t)NPAD * 896];
__device__ __nv_bfloat16 g_ul[(size_t)NPAD * 896];
__device__ __nv_bfloat16 g_Wh[3 * 128 * 1024];   // [L][n][k] transposed, k-contig
__device__ __nv_bfloat16 g_Wl[3 * 128 * 1024];
__device__ float g_bias[3 * 128];
__device__ int   g_counts[NRSEG];                // zero at load; re-zeroed by k_scan
__device__ int   g_offs[NRSEG + 1];
__device__ int   g_cursor[NRSEG];
__device__ unsigned long long g_scanstate[NB1];  // zero at load; re-zeroed by k_fill
__device__ int2  g_edge[EE];                     // (src, w-bits), segment-sorted

// ---------------- helpers ----------------------------------------------------
__device__ __forceinline__ unsigned s2u(const void* p) {
    unsigned a;
    asm("{ .reg .u64 t; cvta.to.shared.u64 t, %1; cvt.u32.u64 %0, t; }" : "=r"(a) : "l"(p));
    return a;
}
__device__ __forceinline__ void cp16(unsigned dst, const void* src) {
    asm volatile("cp.async.cg.shared.global [%0], [%1], 16;" :: "r"(dst), "l"(src) : "memory");
}
__device__ __forceinline__ unsigned long long mk_evict_first() {
    unsigned long long p;
    asm("createpolicy.fractional.L2::evict_first.b64 %0, 1.0;" : "=l"(p));
    return p;
}
__device__ __forceinline__ unsigned long long mk_evict_last() {
    unsigned long long p;
    asm("createpolicy.fractional.L2::evict_last.b64 %0, 1.0;" : "=l"(p));
    return p;
}
__device__ __forceinline__ void cp16_ef(unsigned dst, const void* src,
                                        unsigned long long pol) {
    asm volatile("cp.async.cg.shared.global.L2::cache_hint [%0], [%1], 16, %2;"
                 :: "r"(dst), "l"(src), "l"(pol) : "memory");
}
__device__ __forceinline__ void cp_commit() { asm volatile("cp.async.commit_group;" ::: "memory"); }
__device__ __forceinline__ void cp_wait1()  { asm volatile("cp.async.wait_group 1;" ::: "memory"); }
__device__ __forceinline__ void cp_wait0()  { asm volatile("cp.async.wait_group 0;" ::: "memory"); }
__device__ __forceinline__ void stcs8(void* p, unsigned x, unsigned y) {
    asm volatile("st.global.cs.v2.b32 [%0], {%1, %2};" :: "l"(p), "r"(x), "r"(y) : "memory");
}
__device__ __forceinline__ float4 ldg_el(const float4* p, unsigned long long pol) {
    float4 v;
    asm volatile("ld.global.nc.L2::cache_hint.v4.f32 {%0,%1,%2,%3}, [%4], %5;"
                 : "=f"(v.x), "=f"(v.y), "=f"(v.z), "=f"(v.w) : "l"(p), "l"(pol));
    return v;
}
__device__ __forceinline__ void st_rel(unsigned long long* p, unsigned long long v) {
    asm volatile("st.release.gpu.u64 [%0], %1;" :: "l"(p), "l"(v) : "memory");
}
__device__ __forceinline__ unsigned long long ld_acq(unsigned long long* p) {
    unsigned long long v;
    asm volatile("ld.acquire.gpu.u64 %0, [%1];" : "=l"(v) : "l"(p) : "memory");
    return v;
}
__device__ __forceinline__ void mma16816(float* c, const unsigned* a, const unsigned* b) {
    asm volatile(
        "mma.sync.aligned.m16n8k16.row.col.f32.bf16.bf16.f32 "
        "{%0,%1,%2,%3}, {%4,%5,%6,%7}, {%8,%9}, {%0,%1,%2,%3};"
        : "+f"(c[0]), "+f"(c[1]), "+f"(c[2]), "+f"(c[3])
        : "r"(a[0]), "r"(a[1]), "r"(a[2]), "r"(a[3]), "r"(b[0]), "r"(b[1]));
}

// ---------------- fused setup + hist (launch 0) ------------------------------
__global__ void k_setup(const int* __restrict__ unit_type,
                        const float* __restrict__ emb,
                        const float* __restrict__ Wrel,
                        const float* __restrict__ Wloop,
                        const float* __restrict__ brel,
                        const float* __restrict__ bloop,
                        const int* __restrict__ node_out,
                        const int* __restrict__ rel,
                        float* __restrict__ out_gf) {
    int i = blockIdx.x * blockDim.x + threadIdx.x;
    if (i < NN * DD) {
        int n = i >> 7, d = i & 127;
        float v = emb[unit_type[n] * DD + d];
        g_x[0][i] = v;
        __nv_bfloat16 h = __float2bfloat16(v);
        g_xh[i] = h;
        g_xl[i] = __float2bfloat16(v - __bfloat162float(h));
    }
    if (i < 3 * 128 * 1024) {
        int L = i >> 17;
        int r = i & 131071;
        int n = r >> 10;
        int k = r & 1023;
        float w = (k < 896) ? Wrel[((size_t)L * 896 + k) * 128 + n]
                            : Wloop[((size_t)L * 128 + (k - 896)) * 128 + n];
        __nv_bfloat16 h = __float2bfloat16(w);
        g_Wh[i] = h;
        g_Wl[i] = __float2bfloat16(w - __bfloat162float(h));
    }
    if (i < EE) atomicAdd(&g_counts[node_out[i] * RR + rel[i]], 1);
    if (i < 3 * 128) g_bias[i] = brel[i] + bloop[i];
    if (i < GG * DD) out_gf[i] = 0.0f;
}

// ---------------- scan (launch 1): decoupled lookback; re-zeroes counts ------
__global__ void k_scan() {
    __shared__ int s[SCAN_B];
    __shared__ int s_prefix;
    int bid = blockIdx.x, tid = threadIdx.x;
    int i = bid * SCAN_B + tid;
    int v = (i < NRSEG) ? g_counts[i] : 0;
    if (i < NRSEG) g_counts[i] = 0;           // replay-safety for next run's hist
    s[tid] = v;
    __syncthreads();
    #pragma unroll
    for (int off = 1; off < SCAN_B; off <<= 1) {
        int t = (tid >= off) ? s[tid - off] : 0;
        __syncthreads();
        s[tid] += t;
        __syncthreads();
    }
    int incl  = s[tid];
    int total = s[SCAN_B - 1];

    if (tid == 0) {
        if (bid == 0) {
            st_rel(&g_scanstate[0], ((unsigned long long)total << 2) | 2ull);
            s_prefix = 0;
        } else {
            st_rel(&g_scanstate[bid], ((unsigned long long)total << 2) | 1ull);
            int prefix = 0, j = bid - 1;
            while (true) {
                unsigned long long st = ld_acq(&g_scanstate[j]);
                unsigned f = (unsigned)(st & 3ull);
                if (f == 2u) { prefix += (int)(st >> 2); break; }
                if (f == 1u) { prefix += (int)(st >> 2); --j; }
            }
            st_rel(&g_scanstate[bid],
                   ((unsigned long long)(prefix + total) << 2) | 2ull);
            s_prefix = prefix;
        }
    }
    __syncthreads();
    if (i < NRSEG) {
        int excl = s_prefix + incl - v;
        g_offs[i]   = excl;
        g_cursor[i] = excl;
    }
    if (i == 0) g_offs[NRSEG] = EE;
}

// ---------------- fill (launch 2): CSR edges; re-zeroes scanstate ------------
__global__ void k_fill(const int* __restrict__ node_in,
                       const int* __restrict__ node_out,
                       const int* __restrict__ rel,
                       const float* __restrict__ ew) {
    int i = blockIdx.x * blockDim.x + threadIdx.x;
    if (i < NB1) g_scanstate[i] = 0ull;       // replay-safety for next run's scan
    if (i >= EE) return;
    int seg = node_out[i] * RR + rel[i];
    int p = atomicAdd(&g_cursor[seg], 1);
    g_edge[p] = make_int2(node_in[i], __float_as_int(ew[i]));
}

// ---------------- per-layer edge scatter -> bf16 hi/lo -----------------------
__global__ void k_scatter(int layer) {
    int gw   = (blockIdx.x * blockDim.x + threadIdx.x) >> 5;
    int lane = threadIdx.x & 31;
    if (gw >= NRSEG) return;
    const float4* __restrict__ xv = (const float4*)g_x[layer & 1];
    unsigned long long pol = mk_evict_last();
    int beg = g_offs[gw], end = g_offs[gw + 1];

    float4 a0 = make_float4(0.f, 0.f, 0.f, 0.f);
    float4 a1 = a0, a2 = a0, a3 = a0;
    int e = beg;
    for (; e + 4 <= end; e += 4) {
        int2 m0 = g_edge[e],     m1 = g_edge[e + 1];
        int2 m2 = g_edge[e + 2], m3 = g_edge[e + 3];
        float4 v0 = ldg_el(xv + (size_t)m0.x * 32 + lane, pol);
        float4 v1 = ldg_el(xv + (size_t)m1.x * 32 + lane, pol);
        float4 v2 = ldg_el(xv + (size_t)m2.x * 32 + lane, pol);
        float4 v3 = ldg_el(xv + (size_t)m3.x * 32 + lane, pol);
        float w0 = __int_as_float(m0.y), w1 = __int_as_float(m1.y);
        float w2 = __int_as_float(m2.y), w3 = __int_as_float(m3.y);
        a0.x += v0.x * w0; a0.y += v0.y * w0; a0.z += v0.z * w0; a0.w += v0.w * w0;
        a1.x += v1.x * w1; a1.y += v1.y * w1; a1.z += v1.z * w1; a1.w += v1.w * w1;
        a2.x += v2.x * w2; a2.y += v2.y * w2; a2.z += v2.z * w2; a2.w += v2.w * w2;
        a3.x += v3.x * w3; a3.y += v3.y * w3; a3.z += v3.z * w3; a3.w += v3.w * w3;
    }
    for (; e < end; ++e) {
        int2 m = g_edge[e];
        float4 v = ldg_el(xv + (size_t)m.x * 32 + lane, pol);
        float w = __int_as_float(m.y);
        a0.x += v.x * w; a0.y += v.y * w; a0.z += v.z * w; a0.w += v.w * w;
    }
    float4 acc = make_float4(a0.x + a1.x + a2.x + a3.x,
                             a0.y + a1.y + a2.y + a3.y,
                             a0.z + a1.z + a2.z + a3.z,
                             a0.w + a1.w + a2.w + a3.w);

    size_t o = (size_t)gw * 128 + lane * 4;
    __nv_bfloat16 h0 = __float2bfloat16(acc.x);
    __nv_bfloat16 h1 = __float2bfloat16(acc.y);
    __nv_bfloat16 h2 = __float2bfloat16(acc.z);
    __nv_bfloat16 h3 = __float2bfloat16(acc.w);
    __nv_bfloat162 a, b; a.x = h0; a.y = h1; b.x = h2; b.y = h3;
    __nv_bfloat162 c, d;
    c.x = __float2bfloat16(acc.x - __bfloat162float(h0));
    c.y = __float2bfloat16(acc.y - __bfloat162float(h1));
    d.x = __float2bfloat16(acc.z - __bfloat162float(h2));
    d.y = __float2bfloat16(acc.w - __bfloat162float(h3));
    stcs8(g_uh + o, *(unsigned*)&a, *(unsigned*)&b);
    stcs8(g_ul + o, *(unsigned*)&c, *(unsigned*)&d);
}

// ---------------- mma.sync GEMM: h = [upd|x] @ W + b, relu -------------------
// 256 threads, 2 CTAs/SM (the R12 profile showed 1 CTA/SM left DRAM at 19.7%
// and tensor at 47% — parallelism-starved). BK=32: stage = 4 tiles x 10KB =
// 40KB, double-buffered 80KB -> 2 CTAs/SM, 4 warps/SMSP, 2x cp.async chains.
// 3-term bf16 split into fp32 accum: Ah*Bh + Ah*Bl + Al*Bh.
// Smem tiles [row][40 bf16] (80B stride): word = 20*row + kw -> conflict-free.
#define TSTRIDE 40
#define TBYTES  (128 * TSTRIDE * 2)          // 10240 per tile
#define STAGEB  (4 * TBYTES)                 // Ah,Al,Bh,Bl = 40960
#define SMTOT   (2 * STAGEB)                 // 81920

__device__ __forceinline__ void load_chunk(char* sm, int stage, int c,
                                           int row0, int layer, int tid,
                                           unsigned long long pol) {
    unsigned base = s2u(sm) + (unsigned)stage * STAGEB;
    const __nv_bfloat16* wh = g_Wh + (size_t)layer * 131072;
    const __nv_bfloat16* wl = g_Wl + (size_t)layer * 131072;
    #pragma unroll
    for (int i = 0; i < 8; i++) {
        int idx = tid + 256 * i;             // 2048 x 16B units (4 tiles x 512)
        int arr = idx >> 9;
        int rem = idx & 511;
        int row = rem >> 2;
        int seg = rem & 3;
        unsigned dst = base + (unsigned)arr * TBYTES + row * 80u + seg * 16u;
        if (arr < 2) {                        // A (hi / lo): evict-first stream
            const __nv_bfloat16* src;
            if (c < 28) {
                size_t o = (size_t)(row0 + row) * 896 + c * 32 + seg * 8;
                src = (arr == 0 ? g_uh : g_ul) + o;
            } else {
                size_t o = (size_t)(row0 + row) * 128 + (c - 28) * 32 + seg * 8;
                src = (arr == 0 ? g_xh : g_xl) + o;
            }
            cp16_ef(dst, src, pol);
        } else {                              // B (hi / lo): small, keep cached
            size_t o = (size_t)row * 1024 + c * 32 + seg * 8;
            cp16(dst, (arr == 2 ? wh : wl) + o);
        }
    }
}

__global__ void __launch_bounds__(256, 2)
k_gemm(int layer, float* __restrict__ xout_ext, int dosplit) {
    extern __shared__ char sm[];
    __shared__ float s_bias[128];

    int tid  = threadIdx.x;
    int wid  = tid >> 5, lane = tid & 31;
    int wm   = wid & 1;                      // 2 warps in m (64 rows each)
    int wn   = wid >> 1;                     // 4 warps in n (32 cols each)
    int row0 = blockIdx.x * 128;
    float* __restrict__ xout = xout_ext ? xout_ext : g_x[(layer + 1) & 1];
    unsigned long long pol = mk_evict_first();

    if (tid < 128) s_bias[tid] = g_bias[layer * 128 + tid];

    float acc[4][4][4];
    #pragma unroll
    for (int a = 0; a < 4; a++)
        #pragma unroll
        for (int b = 0; b < 4; b++)
            #pragma unroll
            for (int e = 0; e < 4; e++) acc[a][b][e] = 0.f;

    load_chunk(sm, 0, 0, row0, layer, tid, pol);
    cp_commit();

    const int g = lane >> 2, q = lane & 3;
    for (int c = 0; c < 32; ++c) {
        if (c < 31) {
            load_chunk(sm, (c + 1) & 1, c + 1, row0, layer, tid, pol);
            cp_commit();
            cp_wait1();
        } else {
            cp_wait0();
        }
        __syncthreads();

        const char* st = sm + (c & 1) * STAGEB;
        const char* Ah = st;
        const char* Al = st + TBYTES;
        const char* Bh = st + 2 * TBYTES;
        const char* Bl = st + 3 * TBYTES;

        #pragma unroll
        for (int ks = 0; ks < 2; ++ks) {
            int k0 = ks * 16 + 2 * q;        // bf16 element index in row
            unsigned ah[4][4], al_[4][4], bh[4][2], bl[4][2];
            #pragma unroll
            for (int mt = 0; mt < 4; ++mt) {
                int r = wm * 64 + mt * 16 + g;
                ah[mt][0] = *(const unsigned*)(Ah + r * 80 + k0 * 2);
                ah[mt][1] = *(const unsigned*)(Ah + (r + 8) * 80 + k0 * 2);
                ah[mt][2] = *(const unsigned*)(Ah + r * 80 + (k0 + 8) * 2);
                ah[mt][3] = *(const unsigned*)(Ah + (r + 8) * 80 + (k0 + 8) * 2);
                al_[mt][0] = *(const unsigned*)(Al + r * 80 + k0 * 2);
                al_[mt][1] = *(const unsigned*)(Al + (r + 8) * 80 + k0 * 2);
                al_[mt][2] = *(const unsigned*)(Al + r * 80 + (k0 + 8) * 2);
                al_[mt][3] = *(const unsigned*)(Al + (r + 8) * 80 + (k0 + 8) * 2);
            }
            #pragma unroll
            for (int nt = 0; nt < 4; ++nt) {
                int n = wn * 32 + nt * 8 + g;
                bh[nt][0] = *(const unsigned*)(Bh + n * 80 + k0 * 2);
                bh[nt][1] = *(const unsigned*)(Bh + n * 80 + (k0 + 8) * 2);
                bl[nt][0] = *(const unsigned*)(Bl + n * 80 + k0 * 2);
                bl[nt][1] = *(const unsigned*)(Bl + n * 80 + (k0 + 8) * 2);
            }
            #pragma unroll
            for (int mt = 0; mt < 4; ++mt)
                #pragma unroll
                for (int nt = 0; nt < 4; ++nt) {
                    mma16816(acc[mt][nt], ah[mt],  bh[nt]);
                    mma16816(acc[mt][nt], ah[mt],  bl[nt]);
                    mma16816(acc[mt][nt], al_[mt], bh[nt]);
                }
        }
        __syncthreads();
    }

    // epilogue: bias + relu, fp32 store (+ bf16 split for next layer)
    #pragma unroll
    for (int mt = 0; mt < 4; ++mt) {
        int m0 = row0 + wm * 64 + mt * 16 + g;
        #pragma unroll
        for (int nt = 0; nt < 4; ++nt) {
            int col = wn * 32 + nt * 8 + 2 * q;
            float b0 = s_bias[col], b1 = s_bias[col + 1];
            #pragma unroll
            for (int half = 0; half < 2; ++half) {
                int m = m0 + half * 8;
                if (m >= NN) continue;
                float v0 = fmaxf(acc[mt][nt][2 * half]     + b0, 0.f);
                float v1 = fmaxf(acc[mt][nt][2 * half + 1] + b1, 0.f);
                *(float2*)(xout + (size_t)m * 128 + col) = make_float2(v0, v1);
                if (dosplit) {
                    __nv_bfloat16 h0 = __float2bfloat16(v0);
                    __nv_bfloat16 h1 = __float2bfloat16(v1);
                    __nv_bfloat162 hh; hh.x = h0; hh.y = h1;
                    *(unsigned*)(g_xh + (size_t)m * 128 + col) = *(unsigned*)&hh;
                    __nv_bfloat162 ll;
                    ll.x = __float2bfloat16(v0 - __bfloat162float(h0));
                    ll.y = __float2bfloat16(v1 - __bfloat162float(h1));
                    *(unsigned*)(g_xl + (size_t)m * 128 + col) = *(unsigned*)&ll;
                }
            }
        }
    }
}

// ---------------- graph pooling (node2graph sorted) --------------------------
__global__ void k_segsum(const float* __restrict__ x,
                         const int* __restrict__ n2g,
                         float* __restrict__ out) {
    int d  = threadIdx.x;
    int r0 = blockIdx.x * 512;
    if (r0 >= NN) return;
    int r1 = min(r0 + 512, NN);
    float acc = 0.f;
    int gcur = n2g[r0];
    for (int r = r0; r < r1; ++r) {
        int g = n2g[r];
        if (g != gcur) {
            atomicAdd(&out[gcur * DD + d], acc);
            acc = 0.f; gcur = g;
        }
        acc += x[(size_t)r * DD + d];
    }
    atomicAdd(&out[gcur * DD + d], acc);
}

// ---------------- launch -----------------------------------------------------
// ncu empirically captures launch index 3 — k_scatter(layer 0); next candidate
// to move there once scatter is settled: k_gemm.
extern "C" void kernel_launch(void* const* d_in, const int* in_sizes, int n_in,
                              void* d_out, int out_size) {
    const int*   unit_type   = (const int*)  d_in[0];
    const int*   node_in     = (const int*)  d_in[1];
    const int*   node_out    = (const int*)  d_in[2];
    const int*   relation    = (const int*)  d_in[3];
    const float* edge_weight = (const float*)d_in[4];
    const int*   node2graph  = (const int*)  d_in[5];
    const float* emb         = (const float*)d_in[6];
    const float* W_rel       = (const float*)d_in[7];
    const float* b_rel       = (const float*)d_in[8];
    const float* W_loop      = (const float*)d_in[9];
    const float* b_loop      = (const float*)d_in[10];

    float* out    = (float*)d_out;
    float* out_gf = out;
    float* out_x  = out + GG * DD;

    cudaFuncSetAttribute(k_gemm, cudaFuncAttributeMaxDynamicSharedMemorySize, SMTOT);

    k_setup<<<(NN * DD + 255) / 256, 256>>>(unit_type, emb, W_rel, W_loop,
                                            b_rel, b_loop, node_out, relation,
                                            out_gf);                         // 0
    k_scan<<<NB1, SCAN_B>>>();                                               // 1
    k_fill<<<(EE + 255) / 256, 256>>>(node_in, node_out, relation,
                                      edge_weight);                          // 2

    for (int L = 0; L < 3; ++L) {
        k_scatter<<<(NRSEG * 32 + 255) / 256, 256>>>(L);                     // 3 <- ncu
        float* oext = (L == 2) ? out_x : nullptr;
        k_gemm<<<(NN + 127) / 128, 256, SMTOT>>>(L, oext, (L < 2) ? 1 : 0);
    }

    k_segsum<<<(NN + 511) / 512, 128>>>(out_x, node2graph, out_gf);
}